// round 8
// baseline (speedup 1.0000x reference)
#include <cuda_runtime.h>
#include <cuda_bf16.h>
#include <cstdint>

#define B_  4
#define C_  256
#define N_  4096
#define VSC 8192.0f      // 2^13 scale folded into vs (fp8 range fit)

// ---------------------------------------------------------------------------
// Scratch (__device__ globals; allocation-free rule)
// ---------------------------------------------------------------------------
__device__ __nv_bfloat16  g_xh[(size_t)B_ * N_ * C_];    // x transposed: [b][n][c] bf16 (8MB)
__device__ __nv_bfloat16  g_qkh[B_ * N_ * 64];           // [b][n][0:32)=q,[32:64)=k bf16 (2MB)
__device__ uint8_t        g_vs8[(size_t)B_ * C_ * N_];   // [b][c][m] e4m3 = v/L * 2^13 (4MB)
__device__ float          g_R[B_ * N_];                  // [b][m] = 1/sum_n exp(S[n,m])

// ---------------------------------------------------------------------------
// PTX helpers (base sm_89+ ISA only — harness targets plain sm_103)
// ---------------------------------------------------------------------------
__device__ __forceinline__ uint32_t smem_u32(const void* p) {
    uint32_t a;
    asm("{ .reg .u64 t; cvta.to.shared.u64 t, %1; cvt.u32.u64 %0, t; }" : "=r"(a) : "l"(p));
    return a;
}
#define CP_ASYNC16(dst, src) \
    asm volatile("cp.async.cg.shared.global [%0], [%1], 16;" :: "r"(dst), "l"(src))
#define CP_COMMIT()  asm volatile("cp.async.commit_group;" ::: "memory")
#define CP_WAIT0()   asm volatile("cp.async.wait_group 0;" ::: "memory")

#define LDMATRIX_X4(r0, r1, r2, r3, addr) \
    asm volatile("ldmatrix.sync.aligned.m8n8.x4.shared.b16 {%0,%1,%2,%3}, [%4];" \
                 : "=r"(r0), "=r"(r1), "=r"(r2), "=r"(r3) : "r"(addr))

#define MMA_BF16(d, a, b0v, b1v) \
    asm volatile("mma.sync.aligned.m16n8k16.row.col.f32.bf16.bf16.f32 " \
                 "{%0,%1,%2,%3}, {%4,%5,%6,%7}, {%8,%9}, {%0,%1,%2,%3};" \
                 : "+f"((d)[0]), "+f"((d)[1]), "+f"((d)[2]), "+f"((d)[3]) \
                 : "r"((a)[0]), "r"((a)[1]), "r"((a)[2]), "r"((a)[3]), \
                   "r"(b0v), "r"(b1v))

#define MMA_FP8(d, a, b0v, b1v) \
    asm volatile("mma.sync.aligned.m16n8k32.row.col.f32.e4m3.e4m3.f32 " \
                 "{%0,%1,%2,%3}, {%4,%5,%6,%7}, {%8,%9}, {%0,%1,%2,%3};" \
                 : "+f"((d)[0]), "+f"((d)[1]), "+f"((d)[2]), "+f"((d)[3]) \
                 : "r"((a)[0]), "r"((a)[1]), "r"((a)[2]), "r"((a)[3]), \
                   "r"(b0v), "r"(b1v))

// pack two f32 -> e4m3x2 (lo -> low byte, hi -> high byte)
__device__ __forceinline__ uint16_t f2_e4m3(float lo, float hi) {
    uint16_t r;
    asm("cvt.rn.satfinite.e4m3x2.f32 %0, %1, %2;" : "=h"(r) : "f"(hi), "f"(lo));
    return r;
}

// ---------------------------------------------------------------------------
// K0: transpose + convert x [b][c][n] fp32 -> g_xh [b][n][c] bf16
// ---------------------------------------------------------------------------
__global__ void xpose_kernel(const float* __restrict__ x) {
    __shared__ float xsm[64][68];
    const int n0 = blockIdx.x * 64;
    const int c0 = blockIdx.y * 64;
    const int b  = blockIdx.z;
    const int tid = threadIdx.x;

#pragma unroll
    for (int t = 0; t < 4; t++) {
        int idx = tid + t * 256;
        int cc = idx >> 4, q = idx & 15;
        *(float4*)&xsm[cc][q * 4] = *(const float4*)&x[((size_t)(b * C_ + c0 + cc)) * N_ + n0 + q * 4];
    }
    __syncthreads();
#pragma unroll
    for (int t = 0; t < 8; t++) {
        int idx = tid + t * 256;
        int nl = idx >> 5, pr = idx & 31;
        __nv_bfloat162 p;
        p.x = __float2bfloat16(xsm[pr * 2][nl]);
        p.y = __float2bfloat16(xsm[pr * 2 + 1][nl]);
        *(__nv_bfloat162*)&g_xh[((size_t)(b * N_ + n0 + nl)) * C_ + c0 + pr * 2] = p;
    }
}

// ---------------------------------------------------------------------------
// K1: q/k projection via HMMA (unchanged)
// ---------------------------------------------------------------------------
#define K1_WOFF  36864
#define K1_BOFF  (K1_WOFF + 64 * 528)
#define K1_SMEM  (K1_BOFF + 256)

__global__ __launch_bounds__(256, 1) void proj_qk_mma(
        const float* __restrict__ Wq, const float* __restrict__ bq,
        const float* __restrict__ Wk, const float* __restrict__ bk) {
    extern __shared__ char smem[];
    const uint32_t sbase = smem_u32(smem);
    const uint32_t wsm   = sbase + K1_WOFF;
    float* bsm = (float*)(smem + K1_BOFF);

    const int tid  = threadIdx.x;
    const int wid  = tid >> 5;
    const int lane = tid & 31;
    const int b    = blockIdx.y;
    const int n0   = blockIdx.x * 128;
    const int lrow  = lane & 15;
    const int lcolB = (lane >> 4) * 16;

    const __nv_bfloat16* Xb = g_xh + (size_t)(b * N_ + n0) * C_;

#pragma unroll
    for (int t = 0; t < 4; t++) {
        int idx = tid + t * 256;
        int row = idx >> 3, c16 = idx & 7;
        CP_ASYNC16(sbase + row * 144 + c16 * 16, Xb + (size_t)row * C_ + c16 * 8);
    }
    CP_COMMIT();

#pragma unroll
    for (int t = 0; t < 64; t++) {
        int idx = tid + t * 256;
        int co = idx >> 8, c = idx & 255;
        float v = (co < 32) ? Wq[co * 256 + c] : Wk[(co - 32) * 256 + c];
        *(__nv_bfloat16*)(smem + K1_WOFF + co * 528 + c * 2) = __float2bfloat16(v);
    }
    if (tid < 64) bsm[tid] = (tid < 32) ? bq[tid] : bk[tid - 32];

    float acc[8][4];
#pragma unroll
    for (int nt = 0; nt < 8; nt++)
#pragma unroll
        for (int r = 0; r < 4; r++) acc[nt][r] = 0.0f;

    for (int kc = 0; kc < 4; kc++) {
        const int s = kc & 1;
        CP_WAIT0();
        __syncthreads();

        if (kc + 1 < 4) {
            const uint32_t sd = sbase + (s ^ 1) * 18432;
            const int k0n = (kc + 1) * 64;
#pragma unroll
            for (int t = 0; t < 4; t++) {
                int idx = tid + t * 256;
                int row = idx >> 3, c16 = idx & 7;
                CP_ASYNC16(sd + row * 144 + c16 * 16, Xb + (size_t)row * C_ + k0n + c16 * 8);
            }
            CP_COMMIT();
        }

        const uint32_t sa = sbase + s * 18432;
#pragma unroll
        for (int kk = 0; kk < 4; kk++) {
            uint32_t a[4];
            LDMATRIX_X4(a[0], a[1], a[2], a[3],
                        sa + (wid * 16 + lrow) * 144 + kk * 32 + lcolB);
            uint32_t br[4][4];
#pragma unroll
            for (int bt = 0; bt < 4; bt++)
                LDMATRIX_X4(br[bt][0], br[bt][1], br[bt][2], br[bt][3],
                            wsm + (bt * 16 + lrow) * 528 + (kc * 64 + kk * 16) * 2 + lcolB);
#pragma unroll
            for (int nt = 0; nt < 8; nt++) {
                const int bt = nt >> 1, sel = nt & 1;
                MMA_BF16(acc[nt], a, br[bt][sel], br[bt][sel + 2]);
            }
        }
    }

    const int nrow = n0 + wid * 16 + (lane >> 2);
#pragma unroll
    for (int nt = 0; nt < 8; nt++) {
        const int co = nt * 8 + (lane & 3) * 2;
        const float b0 = bsm[co], b1 = bsm[co + 1];
        __nv_bfloat162 p0, p1;
        p0.x = __float2bfloat16(acc[nt][0] + b0);
        p0.y = __float2bfloat16(acc[nt][1] + b1);
        p1.x = __float2bfloat16(acc[nt][2] + b0);
        p1.y = __float2bfloat16(acc[nt][3] + b1);
        *(__nv_bfloat162*)&g_qkh[((size_t)(b * N_ + nrow)) * 64 + co]       = p0;
        *(__nv_bfloat162*)&g_qkh[((size_t)(b * N_ + nrow + 8)) * 64 + co]   = p1;
    }
}

// ---------------------------------------------------------------------------
// K2': L-sum only; exp on MUFU (unchanged)
// ---------------------------------------------------------------------------
__global__ __launch_bounds__(256, 2) void lsum_mma() {
    __shared__ __align__(16) char ksm_s[64 * 80];
    __shared__ __align__(16) char qsm_s[2 * 128 * 80];
    __shared__ float redsm[8 * 64];
    const uint32_t ksm = smem_u32(ksm_s);
    const uint32_t qsm = smem_u32(qsm_s);

    const int tid  = threadIdx.x;
    const int wid  = tid >> 5;
    const int lane = tid & 31;
    const int b    = blockIdx.y;
    const int m0   = blockIdx.x * 64;
    const int lrow  = lane & 15;
    const int lcolB = (lane >> 4) * 16;

    const __nv_bfloat16* QK = g_qkh + (size_t)b * N_ * 64;

    {
        int row = tid >> 2, c16 = tid & 3;
        CP_ASYNC16(ksm + row * 80 + c16 * 16, QK + (size_t)(m0 + row) * 64 + 32 + c16 * 8);
    }
#pragma unroll
    for (int t = 0; t < 2; t++) {
        int idx = tid + t * 256;
        int row = idx >> 2, c16 = idx & 3;
        CP_ASYNC16(qsm + row * 80 + c16 * 16, QK + (size_t)row * 64 + c16 * 8);
    }
    CP_COMMIT();

    float csum[8][2];
#pragma unroll
    for (int u = 0; u < 8; u++) { csum[u][0] = 0.0f; csum[u][1] = 0.0f; }

    for (int nt = 0; nt < 32; nt++) {
        const int s = nt & 1;
        CP_WAIT0();
        __syncthreads();

        if (nt + 1 < 32) {
            const int n0n = (nt + 1) * 128;
            const uint32_t qd = qsm + (s ^ 1) * 10240;
#pragma unroll
            for (int t = 0; t < 2; t++) {
                int idx = tid + t * 256;
                int row = idx >> 2, c16 = idx & 3;
                CP_ASYNC16(qd + row * 80 + c16 * 16, QK + (size_t)(n0n + row) * 64 + c16 * 8);
            }
            CP_COMMIT();
        }

        const uint32_t qs = qsm + s * 10240;

        float acc[8][4];
#pragma unroll
        for (int u = 0; u < 8; u++)
#pragma unroll
            for (int r = 0; r < 4; r++) acc[u][r] = 0.0f;

#pragma unroll
        for (int kk = 0; kk < 2; kk++) {
            const int kb = kk * 32 + lcolB;
            uint32_t a[4];
            LDMATRIX_X4(a[0], a[1], a[2], a[3], qs + (wid * 16 + lrow) * 80 + kb);
            uint32_t br[4][4];
#pragma unroll
            for (int bt = 0; bt < 4; bt++)
                LDMATRIX_X4(br[bt][0], br[bt][1], br[bt][2], br[bt][3],
                            ksm + (bt * 16 + lrow) * 80 + kb);
#pragma unroll
            for (int u = 0; u < 8; u++) {
                const int bt = u >> 1, sel = u & 1;
                MMA_BF16(acc[u], a, br[bt][sel], br[bt][sel + 2]);
            }
        }

#pragma unroll
        for (int u = 0; u < 8; u++) {
            csum[u][0] += __expf(acc[u][0]) + __expf(acc[u][2]);
            csum[u][1] += __expf(acc[u][1]) + __expf(acc[u][3]);
        }
    }

#pragma unroll
    for (int off = 16; off >= 4; off >>= 1)
#pragma unroll
        for (int u = 0; u < 8; u++) {
            csum[u][0] += __shfl_down_sync(0xffffffffu, csum[u][0], off);
            csum[u][1] += __shfl_down_sync(0xffffffffu, csum[u][1], off);
        }
    if (lane < 4) {
#pragma unroll
        for (int u = 0; u < 8; u++) {
            redsm[wid * 64 + u * 8 + lane * 2 + 0] = csum[u][0];
            redsm[wid * 64 + u * 8 + lane * 2 + 1] = csum[u][1];
        }
    }
    __syncthreads();
    if (tid < 64) {
        float L = 0.0f;
#pragma unroll
        for (int w = 0; w < 8; w++) L += redsm[w * 64 + tid];
        g_R[b * N_ + m0 + tid] = 1.0f / L;
    }
}

// ---------------------------------------------------------------------------
// K3: v projection via HMMA + bias, * (VSC/L), stored TRANSPOSED fp8 e4m3.
// ---------------------------------------------------------------------------
#define K3_WOFF  36864
#define K3_BOFF  (K3_WOFF + 256 * 528)
#define K3_ROFF  (K3_BOFF + 1024)
#define K3_SMEM  (K3_ROFF + 512)

__global__ __launch_bounds__(512, 1) void proj_v_mma(
        const float* __restrict__ Wv, const float* __restrict__ bv) {
    extern __shared__ char smem[];
    const uint32_t sbase = smem_u32(smem);
    const uint32_t wsm   = sbase + K3_WOFF;
    float* bsm = (float*)(smem + K3_BOFF);
    float* rsm = (float*)(smem + K3_ROFF);

    const int tid  = threadIdx.x;
    const int wid  = tid >> 5;
    const int lane = tid & 31;
    const int b    = blockIdx.y;
    const int m0   = blockIdx.x * 128;
    const int warp_m = wid & 3;
    const int warp_n = wid >> 2;
    const int lrow  = lane & 15;
    const int lcolB = (lane >> 4) * 16;

    const __nv_bfloat16* Xb = g_xh + (size_t)(b * N_ + m0) * C_;

#pragma unroll
    for (int t = 0; t < 2; t++) {
        int idx = tid + t * 512;
        int row = idx >> 3, c16 = idx & 7;
        CP_ASYNC16(sbase + row * 144 + c16 * 16, Xb + (size_t)row * C_ + c16 * 8);
    }
    CP_COMMIT();

#pragma unroll
    for (int t = 0; t < 32; t++) {
        int idx = tid + t * 512;
        int row = idx >> 6, q = idx & 63;
        float4 v = *(const float4*)&Wv[row * 256 + q * 4];
        __nv_bfloat162 p0, p1;
        p0.x = __float2bfloat16(v.x); p0.y = __float2bfloat16(v.y);
        p1.x = __float2bfloat16(v.z); p1.y = __float2bfloat16(v.w);
        *(__nv_bfloat162*)(smem + K3_WOFF + row * 528 + q * 8)     = p0;
        *(__nv_bfloat162*)(smem + K3_WOFF + row * 528 + q * 8 + 4) = p1;
    }
    if (tid < 256) bsm[tid] = bv[tid];
    if (tid < 128) rsm[tid] = g_R[b * N_ + m0 + tid] * VSC;

    float acc[2][8][4];
#pragma unroll
    for (int mt = 0; mt < 2; mt++)
#pragma unroll
        for (int nt = 0; nt < 8; nt++)
#pragma unroll
            for (int r = 0; r < 4; r++) acc[mt][nt][r] = 0.0f;

    for (int kc = 0; kc < 4; kc++) {
        const int s = kc & 1;
        CP_WAIT0();
        __syncthreads();

        if (kc + 1 < 4) {
            const uint32_t sd = sbase + (s ^ 1) * 18432;
            const int k0n = (kc + 1) * 64;
#pragma unroll
            for (int t = 0; t < 2; t++) {
                int idx = tid + t * 512;
                int row = idx >> 3, c16 = idx & 7;
                CP_ASYNC16(sd + row * 144 + c16 * 16, Xb + (size_t)row * C_ + k0n + c16 * 8);
            }
            CP_COMMIT();
        }

        const uint32_t sa = sbase + s * 18432;
#pragma unroll
        for (int kk = 0; kk < 4; kk++) {
            uint32_t a[2][4];
#pragma unroll
            for (int mt = 0; mt < 2; mt++)
                LDMATRIX_X4(a[mt][0], a[mt][1], a[mt][2], a[mt][3],
                            sa + (warp_m * 32 + mt * 16 + lrow) * 144 + kk * 32 + lcolB);
            uint32_t br[4][4];
#pragma unroll
            for (int bt = 0; bt < 4; bt++)
                LDMATRIX_X4(br[bt][0], br[bt][1], br[bt][2], br[bt][3],
                            wsm + (warp_n * 64 + bt * 16 + lrow) * 528 + (kc * 64 + kk * 16) * 2 + lcolB);
#pragma unroll
            for (int mt = 0; mt < 2; mt++)
#pragma unroll
                for (int nt = 0; nt < 8; nt++) {
                    const int bt = nt >> 1, sel = nt & 1;
                    MMA_BF16(acc[mt][nt], a[mt], br[bt][sel], br[bt][sel + 2]);
                }
        }
    }

    // epilogue: (acc + bv[c]) * (VSC/L[m]) -> e4m3, transpose to [c][m], store
    char* esp = smem;    // staging: [128 c][144B] (128 fp8 m-values + pad)
#pragma unroll
    for (int h = 0; h < 2; h++) {
        __syncthreads();
        if ((warp_n >> 1) == h) {
            const int cbase = (warp_n & 1) * 64;
#pragma unroll
            for (int mt = 0; mt < 2; mt++) {
                const int m_l = warp_m * 32 + mt * 16 + (lane >> 2);
                const float r0 = rsm[m_l], r1 = rsm[m_l + 8];
#pragma unroll
                for (int nt = 0; nt < 8; nt++) {
                    const int c_l = cbase + nt * 8 + (lane & 3) * 2;
                    const float b0 = bsm[h * 128 + c_l], b1 = bsm[h * 128 + c_l + 1];
                    *(uint8_t*)(esp + c_l * 144 + m_l)           = (uint8_t)f2_e4m3((acc[mt][nt][0] + b0) * r0, 0.0f);
                    *(uint8_t*)(esp + (c_l + 1) * 144 + m_l)     = (uint8_t)f2_e4m3((acc[mt][nt][1] + b1) * r0, 0.0f);
                    *(uint8_t*)(esp + c_l * 144 + m_l + 8)       = (uint8_t)f2_e4m3((acc[mt][nt][2] + b0) * r1, 0.0f);
                    *(uint8_t*)(esp + (c_l + 1) * 144 + m_l + 8) = (uint8_t)f2_e4m3((acc[mt][nt][3] + b1) * r1, 0.0f);
                }
            }
        }
        __syncthreads();
        // copy out: 128 c-rows x 128B
#pragma unroll
        for (int t = 0; t < 2; t++) {
            int idx = tid + t * 512;
            int row = idx >> 3, q = idx & 7;
            float4 v = *(float4*)(esp + row * 144 + q * 16);
            *(float4*)&g_vs8[((size_t)(b * C_ + h * 128 + row)) * N_ + m0 + q * 16] = v;
        }
    }
}

// ---------------------------------------------------------------------------
// K4''': FUSED attention output, fp8 out-GEMM, 2 CTAs/SM.
// Per CTA: 64 n-rows x full C=256; 64 m-chunks of 64.
// smem: q [64x80] @0 | k 2st [64x80] @5120 | vs8 2st [256x80] @15360 |
//       esm8 [64x80] @56320  -> 61440 B
// ---------------------------------------------------------------------------
#define F_QOFF   0
#define F_KOFF   5120
#define F_KSTG   5120
#define F_VOFF   15360
#define F_VSTG   20480
#define F_EOFF   56320
#define F_SMEM   61440

__device__ __forceinline__ void f_load_kv(uint32_t sbase, int stage,
                                          const __nv_bfloat16* QK,
                                          const uint8_t* Vb,
                                          int m0, int tid) {
    uint32_t ks = sbase + F_KOFF + stage * F_KSTG;
    uint32_t vs = sbase + F_VOFF + stage * F_VSTG;
    // k-chunk: 64 m-rows x 32 d bf16 (at +32): 256 x 16B
    {
        int row = tid >> 2, c16 = tid & 3;
        CP_ASYNC16(ks + row * 80 + c16 * 16, QK + (size_t)(m0 + row) * 64 + 32 + c16 * 8);
    }
    // vs-chunk: 256 c-rows x 64 m fp8 (64B): 1024 x 16B
#pragma unroll
    for (int t = 0; t < 4; t++) {
        int idx = tid + t * 256;
        int row = idx >> 2, c16 = idx & 3;
        CP_ASYNC16(vs + row * 80 + c16 * 16, Vb + (size_t)row * N_ + m0 + c16 * 16);
    }
}

__global__ __launch_bounds__(256, 2) void attn_fused(const float* __restrict__ x,
                                                     const float* __restrict__ gamma,
                                                     float* __restrict__ out) {
    extern __shared__ char smem[];
    const uint32_t sbase = smem_u32(smem);

    const int tid  = threadIdx.x;
    const int wid  = tid >> 5;
    const int lane = tid & 31;
    const int b    = blockIdx.y;
    const int n0   = blockIdx.x * 64;
    const int warp_m = wid & 1;      // 32 n-rows
    const int warp_g = wid >> 1;     // 0..3
    const int lrow  = lane & 15;
    const int lcolB = (lane >> 4) * 16;

    const __nv_bfloat16* QK = g_qkh + (size_t)b * N_ * 64;
    const uint8_t* Vb = g_vs8 + (size_t)b * C_ * N_;

    // q-tile (resident): 64 n-rows x 32 d
    {
        int row = tid >> 2, c16 = tid & 3;
        CP_ASYNC16(sbase + F_QOFF + row * 80 + c16 * 16, QK + (size_t)(n0 + row) * 64 + c16 * 8);
    }
    f_load_kv(sbase, 0, QK, Vb, 0, tid);
    CP_COMMIT();

    float acco[2][8][4];
#pragma unroll
    for (int mt = 0; mt < 2; mt++)
#pragma unroll
        for (int nt = 0; nt < 8; nt++)
#pragma unroll
            for (int r = 0; r < 4; r++) acco[mt][nt][r] = 0.0f;

    const uint32_t esm = sbase + F_EOFF;
    char* esp = smem + F_EOFF;

    for (int mc = 0; mc < 64; mc++) {
        const int s = mc & 1;
        CP_WAIT0();
        __syncthreads();

        if (mc + 1 < 64) {
            f_load_kv(sbase, s ^ 1, QK, Vb, (mc + 1) * 64, tid);
            CP_COMMIT();
        }

        const uint32_t ks  = sbase + F_KOFF + s * F_KSTG;
        const uint32_t vsm = sbase + F_VOFF + s * F_VSTG;

        // ---- S = q k^T (bf16; 64n x 64m; warp: 32n x 16m)
        float accs[2][2][4];
#pragma unroll
        for (int mt = 0; mt < 2; mt++)
#pragma unroll
            for (int u = 0; u < 2; u++)
#pragma unroll
                for (int r = 0; r < 4; r++) accs[mt][u][r] = 0.0f;

#pragma unroll
        for (int kk = 0; kk < 2; kk++) {
            const int kb = kk * 32 + lcolB;
            uint32_t a[2][4];
#pragma unroll
            for (int mt = 0; mt < 2; mt++)
                LDMATRIX_X4(a[mt][0], a[mt][1], a[mt][2], a[mt][3],
                            sbase + F_QOFF + (warp_m * 32 + mt * 16 + lrow) * 80 + kb);
            uint32_t bf[4];
            LDMATRIX_X4(bf[0], bf[1], bf[2], bf[3],
                        ks + (warp_g * 16 + lrow) * 80 + kb);
#pragma unroll
            for (int mt = 0; mt < 2; mt++)
#pragma unroll
                for (int u = 0; u < 2; u++)
                    MMA_BF16(accs[mt][u], a[mt], bf[u], bf[u + 2]);
        }

        // ---- exp (MUFU) -> esm e4m3
#pragma unroll
        for (int mt = 0; mt < 2; mt++) {
            const int row = warp_m * 32 + mt * 16 + (lane >> 2);
#pragma unroll
            for (int u = 0; u < 2; u++) {
                const int col = warp_g * 16 + u * 8 + (lane & 3) * 2;
                float e0 = __expf(accs[mt][u][0]);
                float e1 = __expf(accs[mt][u][1]);
                float e2 = __expf(accs[mt][u][2]);
                float e3 = __expf(accs[mt][u][3]);
                *(uint16_t*)(esp + row * 80 + col)       = f2_e4m3(e0, e1);
                *(uint16_t*)(esp + (row + 8) * 80 + col) = f2_e4m3(e2, e3);
            }
        }
        __syncthreads();

        // ---- out += esm(64n x 64m fp8) @ vsm(256c x 64m fp8)^T (warp: 32n x 64c)
#pragma unroll
        for (int kk = 0; kk < 2; kk++) {
            const int kb = kk * 32 + lcolB;      // bytes; 32 fp8 k per mma
            uint32_t ae[2][4];
#pragma unroll
            for (int mt = 0; mt < 2; mt++)
                LDMATRIX_X4(ae[mt][0], ae[mt][1], ae[mt][2], ae[mt][3],
                            esm + (warp_m * 32 + mt * 16 + lrow) * 80 + kb);
            uint32_t be[4][4];
#pragma unroll
            for (int bt = 0; bt < 4; bt++)
                LDMATRIX_X4(be[bt][0], be[bt][1], be[bt][2], be[bt][3],
                            vsm + (warp_g * 64 + bt * 16 + lrow) * 80 + kb);
#pragma unroll
            for (int mt = 0; mt < 2; mt++)
#pragma unroll
                for (int nt = 0; nt < 8; nt++) {
                    const int bt = nt >> 1, sel = nt & 1;
                    MMA_FP8(acco[mt][nt], ae[mt], be[bt][sel], be[bt][sel + 2]);
                }
        }
    }

    // ---------------- epilogue: two c-halves, transpose via smem
    const float g = __ldg(gamma) * (1.0f / VSC);
    float* so = (float*)smem;                 // [128 c][68 n] fp32 = 34816 B

#pragma unroll
    for (int h = 0; h < 2; h++) {
        __syncthreads();
        if ((warp_g >> 1) == h) {
            const int cbase = (warp_g & 1) * 64;
#pragma unroll
            for (int mt = 0; mt < 2; mt++) {
                const int n_l = warp_m * 32 + mt * 16 + (lane >> 2);
#pragma unroll
                for (int nt = 0; nt < 8; nt++) {
                    const int c_l = cbase + nt * 8 + (lane & 3) * 2;
                    so[c_l * 68 + n_l]           = acco[mt][nt][0];
                    so[(c_l + 1) * 68 + n_l]     = acco[mt][nt][1];
                    so[c_l * 68 + n_l + 8]       = acco[mt][nt][2];
                    so[(c_l + 1) * 68 + n_l + 8] = acco[mt][nt][3];
                }
            }
        }
        __syncthreads();
#pragma unroll
        for (int t = 0; t < 8; t++) {
            int idx = tid + t * 256;
            int c_l = idx >> 4, q = idx & 15;
            float4 v = *(float4*)&so[c_l * 68 + q * 4];
            size_t gi = ((size_t)(b * C_ + h * 128 + c_l)) * N_ + n0 + q * 4;
            float4 xv = *(const float4*)&x[gi];
            float4 o;
            o.x = g * v.x + xv.x;
            o.y = g * v.y + xv.y;
            o.z = g * v.z + xv.z;
            o.w = g * v.w + xv.w;
            *(float4*)&out[gi] = o;
        }
    }
}

// ---------------------------------------------------------------------------
extern "C" void kernel_launch(void* const* d_in, const int* in_sizes, int n_in,
                              void* d_out, int out_size) {
    const float* x     = (const float*)d_in[0];
    const float* Wq    = (const float*)d_in[1];
    const float* bq    = (const float*)d_in[2];
    const float* Wk    = (const float*)d_in[3];
    const float* bk    = (const float*)d_in[4];
    const float* Wv    = (const float*)d_in[5];
    const float* bv    = (const float*)d_in[6];
    const float* gamma = (const float*)d_in[7];
    float* out = (float*)d_out;

    cudaFuncSetAttribute(proj_qk_mma, cudaFuncAttributeMaxDynamicSharedMemorySize, K1_SMEM);
    cudaFuncSetAttribute(proj_v_mma,  cudaFuncAttributeMaxDynamicSharedMemorySize, K3_SMEM);
    cudaFuncSetAttribute(attn_fused,  cudaFuncAttributeMaxDynamicSharedMemorySize, F_SMEM);

    xpose_kernel<<<dim3(N_ / 64, C_ / 64, B_), 256>>>(x);
    proj_qk_mma<<<dim3(N_ / 128, B_), 256, K1_SMEM>>>(Wq, bq, Wk, bk);
    lsum_mma<<<dim3(N_ / 64, B_), 256>>>();
    proj_v_mma<<<dim3(N_ / 128, B_), 512, K3_SMEM>>>(Wv, bv);
    attn_fused<<<dim3(N_ / 64, B_), 256, F_SMEM>>>(x, gamma, out);
}

// round 10
// speedup vs baseline: 1.0117x; 1.0117x over previous
#include <cuda_runtime.h>
#include <cuda_bf16.h>
#include <cstdint>

#define B_  4
#define C_  256
#define N_  4096
#define VSC 8192.0f      // 2^13 scale folded into vs (fp8 range fit)

// ---------------------------------------------------------------------------
// Scratch (__device__ globals; allocation-free rule)
// ---------------------------------------------------------------------------
__device__ __nv_bfloat16  g_xh[(size_t)B_ * N_ * C_];    // x transposed: [b][n][c] bf16 (8MB)
__device__ __nv_bfloat16  g_qkh[B_ * N_ * 64];           // [b][n][0:32)=q,[32:64)=k bf16 (2MB)
__device__ uint8_t        g_vs8[(size_t)B_ * C_ * N_];   // [b][c][m] e4m3 = v/L * 2^13 (4MB)
__device__ float          g_R[B_ * N_];                  // [b][m] = 1/sum_n exp(S[n,m])

// ---------------------------------------------------------------------------
// PTX helpers (base sm_89+ ISA only — harness targets plain sm_103)
// ---------------------------------------------------------------------------
__device__ __forceinline__ uint32_t smem_u32(const void* p) {
    uint32_t a;
    asm("{ .reg .u64 t; cvta.to.shared.u64 t, %1; cvt.u32.u64 %0, t; }" : "=r"(a) : "l"(p));
    return a;
}
#define CP_ASYNC16(dst, src) \
    asm volatile("cp.async.cg.shared.global [%0], [%1], 16;" :: "r"(dst), "l"(src))
#define CP_COMMIT()  asm volatile("cp.async.commit_group;" ::: "memory")
#define CP_WAIT0()   asm volatile("cp.async.wait_group 0;" ::: "memory")
#define CP_WAIT1()   asm volatile("cp.async.wait_group 1;" ::: "memory")

#define LDMATRIX_X4(r0, r1, r2, r3, addr) \
    asm volatile("ldmatrix.sync.aligned.m8n8.x4.shared.b16 {%0,%1,%2,%3}, [%4];" \
                 : "=r"(r0), "=r"(r1), "=r"(r2), "=r"(r3) : "r"(addr))

#define MMA_BF16(d, a, b0v, b1v) \
    asm volatile("mma.sync.aligned.m16n8k16.row.col.f32.bf16.bf16.f32 " \
                 "{%0,%1,%2,%3}, {%4,%5,%6,%7}, {%8,%9}, {%0,%1,%2,%3};" \
                 : "+f"((d)[0]), "+f"((d)[1]), "+f"((d)[2]), "+f"((d)[3]) \
                 : "r"((a)[0]), "r"((a)[1]), "r"((a)[2]), "r"((a)[3]), \
                   "r"(b0v), "r"(b1v))

#define MMA_FP8(d, a, b0v, b1v) \
    asm volatile("mma.sync.aligned.m16n8k32.row.col.f32.e4m3.e4m3.f32 " \
                 "{%0,%1,%2,%3}, {%4,%5,%6,%7}, {%8,%9}, {%0,%1,%2,%3};" \
                 : "+f"((d)[0]), "+f"((d)[1]), "+f"((d)[2]), "+f"((d)[3]) \
                 : "r"((a)[0]), "r"((a)[1]), "r"((a)[2]), "r"((a)[3]), \
                   "r"(b0v), "r"(b1v))

// pack two f32 -> e4m3x2
__device__ __forceinline__ uint16_t f2_e4m3(float lo, float hi) {
    uint16_t r;
    asm("cvt.rn.satfinite.e4m3x2.f32 %0, %1, %2;" : "=h"(r) : "f"(hi), "f"(lo));
    return r;
}

// ---------------------------------------------------------------------------
// K0: transpose + convert x [b][c][n] fp32 -> g_xh [b][n][c] bf16
// ---------------------------------------------------------------------------
__global__ void xpose_kernel(const float* __restrict__ x) {
    __shared__ float xsm[64][68];
    const int n0 = blockIdx.x * 64;
    const int c0 = blockIdx.y * 64;
    const int b  = blockIdx.z;
    const int tid = threadIdx.x;

#pragma unroll
    for (int t = 0; t < 4; t++) {
        int idx = tid + t * 256;
        int cc = idx >> 4, q = idx & 15;
        *(float4*)&xsm[cc][q * 4] = *(const float4*)&x[((size_t)(b * C_ + c0 + cc)) * N_ + n0 + q * 4];
    }
    __syncthreads();
#pragma unroll
    for (int t = 0; t < 8; t++) {
        int idx = tid + t * 256;
        int nl = idx >> 5, pr = idx & 31;
        __nv_bfloat162 p;
        p.x = __float2bfloat16(xsm[pr * 2][nl]);
        p.y = __float2bfloat16(xsm[pr * 2 + 1][nl]);
        *(__nv_bfloat162*)&g_xh[((size_t)(b * N_ + n0 + nl)) * C_ + c0 + pr * 2] = p;
    }
}

// ---------------------------------------------------------------------------
// K1: q/k projection via HMMA (unchanged)
// ---------------------------------------------------------------------------
#define K1_WOFF  36864
#define K1_BOFF  (K1_WOFF + 64 * 528)
#define K1_SMEM  (K1_BOFF + 256)

__global__ __launch_bounds__(256, 1) void proj_qk_mma(
        const float* __restrict__ Wq, const float* __restrict__ bq,
        const float* __restrict__ Wk, const float* __restrict__ bk) {
    extern __shared__ char smem[];
    const uint32_t sbase = smem_u32(smem);
    const uint32_t wsm   = sbase + K1_WOFF;
    float* bsm = (float*)(smem + K1_BOFF);

    const int tid  = threadIdx.x;
    const int wid  = tid >> 5;
    const int lane = tid & 31;
    const int b    = blockIdx.y;
    const int n0   = blockIdx.x * 128;
    const int lrow  = lane & 15;
    const int lcolB = (lane >> 4) * 16;

    const __nv_bfloat16* Xb = g_xh + (size_t)(b * N_ + n0) * C_;

#pragma unroll
    for (int t = 0; t < 4; t++) {
        int idx = tid + t * 256;
        int row = idx >> 3, c16 = idx & 7;
        CP_ASYNC16(sbase + row * 144 + c16 * 16, Xb + (size_t)row * C_ + c16 * 8);
    }
    CP_COMMIT();

#pragma unroll
    for (int t = 0; t < 64; t++) {
        int idx = tid + t * 256;
        int co = idx >> 8, c = idx & 255;
        float v = (co < 32) ? Wq[co * 256 + c] : Wk[(co - 32) * 256 + c];
        *(__nv_bfloat16*)(smem + K1_WOFF + co * 528 + c * 2) = __float2bfloat16(v);
    }
    if (tid < 64) bsm[tid] = (tid < 32) ? bq[tid] : bk[tid - 32];

    float acc[8][4];
#pragma unroll
    for (int nt = 0; nt < 8; nt++)
#pragma unroll
        for (int r = 0; r < 4; r++) acc[nt][r] = 0.0f;

    for (int kc = 0; kc < 4; kc++) {
        const int s = kc & 1;
        CP_WAIT0();
        __syncthreads();

        if (kc + 1 < 4) {
            const uint32_t sd = sbase + (s ^ 1) * 18432;
            const int k0n = (kc + 1) * 64;
#pragma unroll
            for (int t = 0; t < 4; t++) {
                int idx = tid + t * 256;
                int row = idx >> 3, c16 = idx & 7;
                CP_ASYNC16(sd + row * 144 + c16 * 16, Xb + (size_t)row * C_ + k0n + c16 * 8);
            }
            CP_COMMIT();
        }

        const uint32_t sa = sbase + s * 18432;
#pragma unroll
        for (int kk = 0; kk < 4; kk++) {
            uint32_t a[4];
            LDMATRIX_X4(a[0], a[1], a[2], a[3],
                        sa + (wid * 16 + lrow) * 144 + kk * 32 + lcolB);
            uint32_t br[4][4];
#pragma unroll
            for (int bt = 0; bt < 4; bt++)
                LDMATRIX_X4(br[bt][0], br[bt][1], br[bt][2], br[bt][3],
                            wsm + (bt * 16 + lrow) * 528 + (kc * 64 + kk * 16) * 2 + lcolB);
#pragma unroll
            for (int nt = 0; nt < 8; nt++) {
                const int bt = nt >> 1, sel = nt & 1;
                MMA_BF16(acc[nt], a, br[bt][sel], br[bt][sel + 2]);
            }
        }
    }

    const int nrow = n0 + wid * 16 + (lane >> 2);
#pragma unroll
    for (int nt = 0; nt < 8; nt++) {
        const int co = nt * 8 + (lane & 3) * 2;
        const float b0 = bsm[co], b1 = bsm[co + 1];
        __nv_bfloat162 p0, p1;
        p0.x = __float2bfloat16(acc[nt][0] + b0);
        p0.y = __float2bfloat16(acc[nt][1] + b1);
        p1.x = __float2bfloat16(acc[nt][2] + b0);
        p1.y = __float2bfloat16(acc[nt][3] + b1);
        *(__nv_bfloat162*)&g_qkh[((size_t)(b * N_ + nrow)) * 64 + co]       = p0;
        *(__nv_bfloat162*)&g_qkh[((size_t)(b * N_ + nrow + 8)) * 64 + co]   = p1;
    }
}

// ---------------------------------------------------------------------------
// K2': L-sum only; exp on MUFU (unchanged)
// ---------------------------------------------------------------------------
__global__ __launch_bounds__(256, 2) void lsum_mma() {
    __shared__ __align__(16) char ksm_s[64 * 80];
    __shared__ __align__(16) char qsm_s[2 * 128 * 80];
    __shared__ float redsm[8 * 64];
    const uint32_t ksm = smem_u32(ksm_s);
    const uint32_t qsm = smem_u32(qsm_s);

    const int tid  = threadIdx.x;
    const int wid  = tid >> 5;
    const int lane = tid & 31;
    const int b    = blockIdx.y;
    const int m0   = blockIdx.x * 64;
    const int lrow  = lane & 15;
    const int lcolB = (lane >> 4) * 16;

    const __nv_bfloat16* QK = g_qkh + (size_t)b * N_ * 64;

    {
        int row = tid >> 2, c16 = tid & 3;
        CP_ASYNC16(ksm + row * 80 + c16 * 16, QK + (size_t)(m0 + row) * 64 + 32 + c16 * 8);
    }
#pragma unroll
    for (int t = 0; t < 2; t++) {
        int idx = tid + t * 256;
        int row = idx >> 2, c16 = idx & 3;
        CP_ASYNC16(qsm + row * 80 + c16 * 16, QK + (size_t)row * 64 + c16 * 8);
    }
    CP_COMMIT();

    float csum[8][2];
#pragma unroll
    for (int u = 0; u < 8; u++) { csum[u][0] = 0.0f; csum[u][1] = 0.0f; }

    for (int nt = 0; nt < 32; nt++) {
        const int s = nt & 1;
        CP_WAIT0();
        __syncthreads();

        if (nt + 1 < 32) {
            const int n0n = (nt + 1) * 128;
            const uint32_t qd = qsm + (s ^ 1) * 10240;
#pragma unroll
            for (int t = 0; t < 2; t++) {
                int idx = tid + t * 256;
                int row = idx >> 2, c16 = idx & 3;
                CP_ASYNC16(qd + row * 80 + c16 * 16, QK + (size_t)(n0n + row) * 64 + c16 * 8);
            }
            CP_COMMIT();
        }

        const uint32_t qs = qsm + s * 10240;

        float acc[8][4];
#pragma unroll
        for (int u = 0; u < 8; u++)
#pragma unroll
            for (int r = 0; r < 4; r++) acc[u][r] = 0.0f;

#pragma unroll
        for (int kk = 0; kk < 2; kk++) {
            const int kb = kk * 32 + lcolB;
            uint32_t a[4];
            LDMATRIX_X4(a[0], a[1], a[2], a[3], qs + (wid * 16 + lrow) * 80 + kb);
            uint32_t br[4][4];
#pragma unroll
            for (int bt = 0; bt < 4; bt++)
                LDMATRIX_X4(br[bt][0], br[bt][1], br[bt][2], br[bt][3],
                            ksm + (bt * 16 + lrow) * 80 + kb);
#pragma unroll
            for (int u = 0; u < 8; u++) {
                const int bt = u >> 1, sel = u & 1;
                MMA_BF16(acc[u], a, br[bt][sel], br[bt][sel + 2]);
            }
        }

#pragma unroll
        for (int u = 0; u < 8; u++) {
            csum[u][0] += __expf(acc[u][0]) + __expf(acc[u][2]);
            csum[u][1] += __expf(acc[u][1]) + __expf(acc[u][3]);
        }
    }

#pragma unroll
    for (int off = 16; off >= 4; off >>= 1)
#pragma unroll
        for (int u = 0; u < 8; u++) {
            csum[u][0] += __shfl_down_sync(0xffffffffu, csum[u][0], off);
            csum[u][1] += __shfl_down_sync(0xffffffffu, csum[u][1], off);
        }
    if (lane < 4) {
#pragma unroll
        for (int u = 0; u < 8; u++) {
            redsm[wid * 64 + u * 8 + lane * 2 + 0] = csum[u][0];
            redsm[wid * 64 + u * 8 + lane * 2 + 1] = csum[u][1];
        }
    }
    __syncthreads();
    if (tid < 64) {
        float L = 0.0f;
#pragma unroll
        for (int w = 0; w < 8; w++) L += redsm[w * 64 + tid];
        g_R[b * N_ + m0 + tid] = 1.0f / L;
    }
}

// ---------------------------------------------------------------------------
// K3: v projection via HMMA + bias, * (VSC/L), stored TRANSPOSED fp8 e4m3.
// ---------------------------------------------------------------------------
#define K3_WOFF  36864
#define K3_BOFF  (K3_WOFF + 256 * 528)
#define K3_ROFF  (K3_BOFF + 1024)
#define K3_SMEM  (K3_ROFF + 512)

__global__ __launch_bounds__(512, 1) void proj_v_mma(
        const float* __restrict__ Wv, const float* __restrict__ bv) {
    extern __shared__ char smem[];
    const uint32_t sbase = smem_u32(smem);
    const uint32_t wsm   = sbase + K3_WOFF;
    float* bsm = (float*)(smem + K3_BOFF);
    float* rsm = (float*)(smem + K3_ROFF);

    const int tid  = threadIdx.x;
    const int wid  = tid >> 5;
    const int lane = tid & 31;
    const int b    = blockIdx.y;
    const int m0   = blockIdx.x * 128;
    const int warp_m = wid & 3;
    const int warp_n = wid >> 2;
    const int lrow  = lane & 15;
    const int lcolB = (lane >> 4) * 16;

    const __nv_bfloat16* Xb = g_xh + (size_t)(b * N_ + m0) * C_;

#pragma unroll
    for (int t = 0; t < 2; t++) {
        int idx = tid + t * 512;
        int row = idx >> 3, c16 = idx & 7;
        CP_ASYNC16(sbase + row * 144 + c16 * 16, Xb + (size_t)row * C_ + c16 * 8);
    }
    CP_COMMIT();

#pragma unroll
    for (int t = 0; t < 32; t++) {
        int idx = tid + t * 512;
        int row = idx >> 6, q = idx & 63;
        float4 v = *(const float4*)&Wv[row * 256 + q * 4];
        __nv_bfloat162 p0, p1;
        p0.x = __float2bfloat16(v.x); p0.y = __float2bfloat16(v.y);
        p1.x = __float2bfloat16(v.z); p1.y = __float2bfloat16(v.w);
        *(__nv_bfloat162*)(smem + K3_WOFF + row * 528 + q * 8)     = p0;
        *(__nv_bfloat162*)(smem + K3_WOFF + row * 528 + q * 8 + 4) = p1;
    }
    if (tid < 256) bsm[tid] = bv[tid];
    if (tid < 128) rsm[tid] = g_R[b * N_ + m0 + tid] * VSC;

    float acc[2][8][4];
#pragma unroll
    for (int mt = 0; mt < 2; mt++)
#pragma unroll
        for (int nt = 0; nt < 8; nt++)
#pragma unroll
            for (int r = 0; r < 4; r++) acc[mt][nt][r] = 0.0f;

    for (int kc = 0; kc < 4; kc++) {
        const int s = kc & 1;
        CP_WAIT0();
        __syncthreads();

        if (kc + 1 < 4) {
            const uint32_t sd = sbase + (s ^ 1) * 18432;
            const int k0n = (kc + 1) * 64;
#pragma unroll
            for (int t = 0; t < 2; t++) {
                int idx = tid + t * 512;
                int row = idx >> 3, c16 = idx & 7;
                CP_ASYNC16(sd + row * 144 + c16 * 16, Xb + (size_t)row * C_ + k0n + c16 * 8);
            }
            CP_COMMIT();
        }

        const uint32_t sa = sbase + s * 18432;
#pragma unroll
        for (int kk = 0; kk < 4; kk++) {
            uint32_t a[2][4];
#pragma unroll
            for (int mt = 0; mt < 2; mt++)
                LDMATRIX_X4(a[mt][0], a[mt][1], a[mt][2], a[mt][3],
                            sa + (warp_m * 32 + mt * 16 + lrow) * 144 + kk * 32 + lcolB);
            uint32_t br[4][4];
#pragma unroll
            for (int bt = 0; bt < 4; bt++)
                LDMATRIX_X4(br[bt][0], br[bt][1], br[bt][2], br[bt][3],
                            wsm + (warp_n * 64 + bt * 16 + lrow) * 528 + (kc * 64 + kk * 16) * 2 + lcolB);
#pragma unroll
            for (int mt = 0; mt < 2; mt++)
#pragma unroll
                for (int nt = 0; nt < 8; nt++) {
                    const int bt = nt >> 1, sel = nt & 1;
                    MMA_BF16(acc[mt][nt], a[mt], br[bt][sel], br[bt][sel + 2]);
                }
        }
    }

    // epilogue: (acc + bv[c]) * (VSC/L[m]) -> e4m3, transpose to [c][m], store
    char* esp = smem;
#pragma unroll
    for (int h = 0; h < 2; h++) {
        __syncthreads();
        if ((warp_n >> 1) == h) {
            const int cbase = (warp_n & 1) * 64;
#pragma unroll
            for (int mt = 0; mt < 2; mt++) {
                const int m_l = warp_m * 32 + mt * 16 + (lane >> 2);
                const float r0 = rsm[m_l], r1 = rsm[m_l + 8];
#pragma unroll
                for (int nt = 0; nt < 8; nt++) {
                    const int c_l = cbase + nt * 8 + (lane & 3) * 2;
                    const float b0 = bsm[h * 128 + c_l], b1 = bsm[h * 128 + c_l + 1];
                    *(uint8_t*)(esp + c_l * 144 + m_l)           = (uint8_t)f2_e4m3((acc[mt][nt][0] + b0) * r0, 0.0f);
                    *(uint8_t*)(esp + (c_l + 1) * 144 + m_l)     = (uint8_t)f2_e4m3((acc[mt][nt][1] + b1) * r0, 0.0f);
                    *(uint8_t*)(esp + c_l * 144 + m_l + 8)       = (uint8_t)f2_e4m3((acc[mt][nt][2] + b0) * r1, 0.0f);
                    *(uint8_t*)(esp + (c_l + 1) * 144 + m_l + 8) = (uint8_t)f2_e4m3((acc[mt][nt][3] + b1) * r1, 0.0f);
                }
            }
        }
        __syncthreads();
#pragma unroll
        for (int t = 0; t < 2; t++) {
            int idx = tid + t * 512;
            int row = idx >> 3, q = idx & 7;
            float4 v = *(float4*)(esp + row * 144 + q * 16);
            *(float4*)&g_vs8[((size_t)(b * C_ + h * 128 + row)) * N_ + m0 + q * 16] = v;
        }
    }
}

// ---------------------------------------------------------------------------
// K4: FUSED attention output, SW-PIPELINED: out-mma(k) issues before
// S(k+1)+exp, single barrier/chunk. esm double-buffered, k/vs triple-buffered.
// smem: q [64x80] @0 | k 3st @5120 | vs8 3st @20480 | esm8 2st @81920 -> 92160
// ---------------------------------------------------------------------------
#define F_QOFF   0
#define F_KOFF   5120
#define F_KSTG   5120
#define F_VOFF   20480
#define F_VSTG   20480
#define F_EOFF   81920
#define F_ESTG   5120
#define F_SMEM   92160

__device__ __forceinline__ void f_load_kv(uint32_t sbase, int stage,
                                          const __nv_bfloat16* QK,
                                          const uint8_t* Vb,
                                          int m0, int tid) {
    uint32_t ks = sbase + F_KOFF + stage * F_KSTG;
    uint32_t vs = sbase + F_VOFF + stage * F_VSTG;
    {
        int row = tid >> 2, c16 = tid & 3;
        CP_ASYNC16(ks + row * 80 + c16 * 16, QK + (size_t)(m0 + row) * 64 + 32 + c16 * 8);
    }
#pragma unroll
    for (int t = 0; t < 4; t++) {
        int idx = tid + t * 256;
        int row = idx >> 2, c16 = idx & 3;
        CP_ASYNC16(vs + row * 80 + c16 * 16, Vb + (size_t)row * N_ + m0 + c16 * 16);
    }
}

// S = q k^T (bf16) -> exp (MUFU) -> esm buffer (e4m3)
__device__ __forceinline__ void f_s_phase(uint32_t sbase, char* smem, int kst, int ebuf,
                                          int warp_m, int warp_g, int lane,
                                          int lrow, int lcolB) {
    const uint32_t ks = sbase + F_KOFF + kst * F_KSTG;
    char* esp = smem + F_EOFF + ebuf * F_ESTG;

    float accs[2][2][4];
#pragma unroll
    for (int mt = 0; mt < 2; mt++)
#pragma unroll
        for (int u = 0; u < 2; u++)
#pragma unroll
            for (int r = 0; r < 4; r++) accs[mt][u][r] = 0.0f;

#pragma unroll
    for (int kk = 0; kk < 2; kk++) {
        const int kb = kk * 32 + lcolB;
        uint32_t a[2][4];
#pragma unroll
        for (int mt = 0; mt < 2; mt++)
            LDMATRIX_X4(a[mt][0], a[mt][1], a[mt][2], a[mt][3],
                        sbase + F_QOFF + (warp_m * 32 + mt * 16 + lrow) * 80 + kb);
        uint32_t bf[4];
        LDMATRIX_X4(bf[0], bf[1], bf[2], bf[3],
                    ks + (warp_g * 16 + lrow) * 80 + kb);
#pragma unroll
        for (int mt = 0; mt < 2; mt++)
#pragma unroll
            for (int u = 0; u < 2; u++)
                MMA_BF16(accs[mt][u], a[mt], bf[u], bf[u + 2]);
    }

#pragma unroll
    for (int mt = 0; mt < 2; mt++) {
        const int row = warp_m * 32 + mt * 16 + (lane >> 2);
#pragma unroll
        for (int u = 0; u < 2; u++) {
            const int col = warp_g * 16 + u * 8 + (lane & 3) * 2;
            float e0 = __expf(accs[mt][u][0]);
            float e1 = __expf(accs[mt][u][1]);
            float e2 = __expf(accs[mt][u][2]);
            float e3 = __expf(accs[mt][u][3]);
            *(uint16_t*)(esp + row * 80 + col)       = f2_e4m3(e0, e1);
            *(uint16_t*)(esp + (row + 8) * 80 + col) = f2_e4m3(e2, e3);
        }
    }
}

// out += esm @ vs^T (fp8)
__device__ __forceinline__ void f_out_phase(uint32_t sbase, int vst, int ebuf,
                                            float acco[2][8][4],
                                            int warp_m, int warp_g,
                                            int lrow, int lcolB) {
    const uint32_t vsm = sbase + F_VOFF + vst * F_VSTG;
    const uint32_t esm = sbase + F_EOFF + ebuf * F_ESTG;
#pragma unroll
    for (int kk = 0; kk < 2; kk++) {
        const int kb = kk * 32 + lcolB;
        uint32_t ae[2][4];
#pragma unroll
        for (int mt = 0; mt < 2; mt++)
            LDMATRIX_X4(ae[mt][0], ae[mt][1], ae[mt][2], ae[mt][3],
                        esm + (warp_m * 32 + mt * 16 + lrow) * 80 + kb);
        uint32_t be[4][4];
#pragma unroll
        for (int bt = 0; bt < 4; bt++)
            LDMATRIX_X4(be[bt][0], be[bt][1], be[bt][2], be[bt][3],
                        vsm + (warp_g * 64 + bt * 16 + lrow) * 80 + kb);
#pragma unroll
        for (int mt = 0; mt < 2; mt++)
#pragma unroll
            for (int nt = 0; nt < 8; nt++) {
                const int bt = nt >> 1, sel = nt & 1;
                MMA_FP8(acco[mt][nt], ae[mt], be[bt][sel], be[bt][sel + 2]);
            }
    }
}

__global__ __launch_bounds__(256, 2) void attn_fused(const float* __restrict__ x,
                                                     const float* __restrict__ gamma,
                                                     float* __restrict__ out) {
    extern __shared__ char smem[];
    const uint32_t sbase = smem_u32(smem);

    const int tid  = threadIdx.x;
    const int wid  = tid >> 5;
    const int lane = tid & 31;
    const int b    = blockIdx.y;
    const int n0   = blockIdx.x * 64;
    const int warp_m = wid & 1;
    const int warp_g = wid >> 1;
    const int lrow  = lane & 15;
    const int lcolB = (lane >> 4) * 16;

    const __nv_bfloat16* QK = g_qkh + (size_t)b * N_ * 64;
    const uint8_t* Vb = g_vs8 + (size_t)b * C_ * N_;

    // prologue: q + chunk0 (group 0), chunk1 (group 1)
    {
        int row = tid >> 2, c16 = tid & 3;
        CP_ASYNC16(sbase + F_QOFF + row * 80 + c16 * 16, QK + (size_t)(n0 + row) * 64 + c16 * 8);
    }
    f_load_kv(sbase, 0, QK, Vb, 0, tid);
    CP_COMMIT();
    f_load_kv(sbase, 1, QK, Vb, 64, tid);
    CP_COMMIT();

    float acco[2][8][4];
#pragma unroll
    for (int mt = 0; mt < 2; mt++)
#pragma unroll
        for (int nt = 0; nt < 8; nt++)
#pragma unroll
            for (int r = 0; r < 4; r++) acco[mt][nt][r] = 0.0f;

    CP_WAIT1();                 // chunk 0 (and q) resident
    __syncthreads();
    f_s_phase(sbase, smem, 0, 0, warp_m, warp_g, lane, lrow, lcolB);
    __syncthreads();            // esm buf 0 visible

    int st2 = 2;                // stage of chunk mc+2
    for (int mc = 0; mc < 64; mc++) {
        // prefetch chunk mc+2 into stage (mc+2)%3 (free: last read ended iter mc-1)
        if (mc + 2 < 64) {
            f_load_kv(sbase, st2, QK, Vb, (mc + 2) * 64, tid);
            CP_COMMIT();
        }

        // out-mma(mc): no new deps — fills the tensor pipe first
        f_out_phase(sbase, mc % 3, mc & 1, acco, warp_m, warp_g, lrow, lcolB);

        // S(mc+1) -> other esm buffer (needs chunk mc+1 loaded)
        if (mc + 1 < 64) {
            if (mc + 2 < 64) { CP_WAIT1(); } else { CP_WAIT0(); }
            f_s_phase(sbase, smem, (mc + 1) % 3, (mc + 1) & 1,
                      warp_m, warp_g, lane, lrow, lcolB);
        }
        __syncthreads();

        if (++st2 == 3) st2 = 0;
    }

    // ---------------- epilogue: two c-halves, transpose via smem
    const float g = __ldg(gamma) * (1.0f / VSC);
    float* so = (float*)smem;                 // [128 c][68 n] fp32 = 34816 B

#pragma unroll
    for (int h = 0; h < 2; h++) {
        __syncthreads();
        if ((warp_g >> 1) == h) {
            const int cbase = (warp_g & 1) * 64;
#pragma unroll
            for (int mt = 0; mt < 2; mt++) {
                const int n_l = warp_m * 32 + mt * 16 + (lane >> 2);
#pragma unroll
                for (int nt = 0; nt < 8; nt++) {
                    const int c_l = cbase + nt * 8 + (lane & 3) * 2;
                    so[c_l * 68 + n_l]           = acco[mt][nt][0];
                    so[(c_l + 1) * 68 + n_l]     = acco[mt][nt][1];
                    so[c_l * 68 + n_l + 8]       = acco[mt][nt][2];
                    so[(c_l + 1) * 68 + n_l + 8] = acco[mt][nt][3];
                }
            }
        }
        __syncthreads();
#pragma unroll
        for (int t = 0; t < 8; t++) {
            int idx = tid + t * 256;
            int c_l = idx >> 4, q = idx & 15;
            float4 v = *(float4*)&so[c_l * 68 + q * 4];
            size_t gi = ((size_t)(b * C_ + h * 128 + c_l)) * N_ + n0 + q * 4;
            float4 xv = *(const float4*)&x[gi];
            float4 o;
            o.x = g * v.x + xv.x;
            o.y = g * v.y + xv.y;
            o.z = g * v.z + xv.z;
            o.w = g * v.w + xv.w;
            *(float4*)&out[gi] = o;
        }
    }
}

// ---------------------------------------------------------------------------
extern "C" void kernel_launch(void* const* d_in, const int* in_sizes, int n_in,
                              void* d_out, int out_size) {
    const float* x     = (const float*)d_in[0];
    const float* Wq    = (const float*)d_in[1];
    const float* bq    = (const float*)d_in[2];
    const float* Wk    = (const float*)d_in[3];
    const float* bk    = (const float*)d_in[4];
    const float* Wv    = (const float*)d_in[5];
    const float* bv    = (const float*)d_in[6];
    const float* gamma = (const float*)d_in[7];
    float* out = (float*)d_out;

    cudaFuncSetAttribute(proj_qk_mma, cudaFuncAttributeMaxDynamicSharedMemorySize, K1_SMEM);
    cudaFuncSetAttribute(proj_v_mma,  cudaFuncAttributeMaxDynamicSharedMemorySize, K3_SMEM);
    cudaFuncSetAttribute(attn_fused,  cudaFuncAttributeMaxDynamicSharedMemorySize, F_SMEM);

    xpose_kernel<<<dim3(N_ / 64, C_ / 64, B_), 256>>>(x);
    proj_qk_mma<<<dim3(N_ / 128, B_), 256, K1_SMEM>>>(Wq, bq, Wk, bk);
    lsum_mma<<<dim3(N_ / 64, B_), 256>>>();
    proj_v_mma<<<dim3(N_ / 128, B_), 512, K3_SMEM>>>(Wv, bv);
    attn_fused<<<dim3(N_ / 64, B_), 256, F_SMEM>>>(x, gamma, out);
}